// round 15
// baseline (speedup 1.0000x reference)
#include <cuda_runtime.h>
#include <cuda_fp16.h>
#include <cstdint>

#define NTOK 8192
#define DIMC 1024
#define HIDC 4096
#define NEXP 8
#define BM 128
#define MAXT 72
#define WSZ (NEXP * DIMC * HIDC)
#define NKT1 16

#define NB_W 240
#define WO_0 NB_W
#define NB_WO 144
#define G1_0 (WO_0 + NB_WO)
#define NB_G1 (MAXT * 64)
#define G2_0 (G1_0 + NB_G1)
#define NB_G2 (MAXT * 8)
#define NB_TOT (G2_0 + NB_G2)

// ---------------- persistent device scratch ----------------
__device__ int g_order[NTOK];
__device__ int g_tile_expert[MAXT];
__device__ int g_tile_row0[MAXT];
__device__ int g_tile_rows[MAXT];
__device__ int g_ntiles;
__device__ int g_tile_done[MAXT];
__device__ int g_wo_done;
__device__ int g_kdone[NKT1];   // weight-conversion frontier per k-tile
__device__ int g_prod_cnt;
__device__ int g_all_done;
__device__ __half g_hbuf[(size_t)(NTOK + BM) * HIDC];
__device__ __half g_whg[WSZ];
__device__ __half g_whi[WSZ];
__device__ __half g_who[WSZ];
__device__ __half g_xh[NTOK * DIMC];

// ---------------- helpers ----------------
__device__ __forceinline__ uint32_t su32(const void* p) {
    uint32_t a;
    asm("{ .reg .u64 t; cvta.to.shared.u64 t, %1; cvt.u32.u64 %0, t; }" : "=r"(a) : "l"(p));
    return a;
}
__device__ __forceinline__ void ldsm4(uint32_t r[4], uint32_t a) {
    asm volatile("ldmatrix.sync.aligned.m8n8.x4.shared.b16 {%0,%1,%2,%3}, [%4];"
                 : "=r"(r[0]), "=r"(r[1]), "=r"(r[2]), "=r"(r[3]) : "r"(a));
}
__device__ __forceinline__ void ldsm4t(uint32_t r[4], uint32_t a) {
    asm volatile("ldmatrix.sync.aligned.m8n8.x4.trans.shared.b16 {%0,%1,%2,%3}, [%4];"
                 : "=r"(r[0]), "=r"(r[1]), "=r"(r[2]), "=r"(r[3]) : "r"(a));
}
__device__ __forceinline__ void mma16816(float c[4], const uint32_t a[4], const uint32_t* b) {
    asm volatile(
        "mma.sync.aligned.m16n8k16.row.col.f32.f16.f16.f32 "
        "{%0,%1,%2,%3}, {%4,%5,%6,%7}, {%8,%9}, {%0,%1,%2,%3};"
        : "+f"(c[0]), "+f"(c[1]), "+f"(c[2]), "+f"(c[3])
        : "r"(a[0]), "r"(a[1]), "r"(a[2]), "r"(a[3]), "r"(b[0]), "r"(b[1]));
}
__device__ __forceinline__ uint32_t f2h2(float a, float b) {
    __half2 h = __floats2half2_rn(a, b);
    return *(uint32_t*)&h;
}
__device__ __forceinline__ uint4 pack8f(const float4& u, const float4& v) {
    uint4 o;
    o.x = f2h2(u.x, u.y); o.y = f2h2(u.z, u.w);
    o.z = f2h2(v.x, v.y); o.w = f2h2(v.z, v.w);
    return o;
}
#define CP16(dst, src) asm volatile("cp.async.cg.shared.global [%0], [%1], 16;" :: "r"(dst), "l"(src))
#define CPCOMMIT() asm volatile("cp.async.commit_group;" ::: "memory")
#define CPWAIT1() asm volatile("cp.async.wait_group 1;" ::: "memory")

// ---------------- kernel 1: x fp32->fp16 + routing + counter resets ----------------
__global__ void __launch_bounds__(256) x_route_kernel(
    const float* __restrict__ x, const int* __restrict__ rm)
{
    __shared__ int cnt[NEXP], off[NEXP], cur[NEXP];
    int tid = threadIdx.x;
    if (blockIdx.x == gridDim.x - 1) {
        if (tid < MAXT) g_tile_done[tid] = 0;
        if (tid < NKT1) g_kdone[tid] = 0;
        if (tid == 0) { g_wo_done = 0; g_prod_cnt = 0; g_all_done = 0; }
        if (tid < NEXP) cnt[tid] = 0;
        __syncthreads();
        for (int i = tid; i < NTOK; i += blockDim.x) atomicAdd(&cnt[rm[i]], 1);
        __syncthreads();
        if (tid == 0) {
            int run = 0, nt = 0;
            for (int e = 0; e < NEXP; e++) {
                off[e] = run;
                int rem = cnt[e], r = run;
                while (rem > 0) {
                    g_tile_expert[nt] = e;
                    g_tile_row0[nt] = r;
                    g_tile_rows[nt] = rem < BM ? rem : BM;
                    r += BM; rem -= BM; nt++;
                }
                run += cnt[e];
            }
            g_ntiles = nt;
        }
        __syncthreads();
        if (tid < NEXP) cur[tid] = off[tid];
        __syncthreads();
        for (int i = tid; i < NTOK; i += blockDim.x) {
            int p = atomicAdd(&cur[rm[i]], 1);
            g_order[p] = i;
        }
        return;
    }
    size_t stride = (size_t)(gridDim.x - 1) * blockDim.x;
    size_t t0 = (size_t)blockIdx.x * blockDim.x + tid;
#pragma unroll 2
    for (size_t i = t0; i < (size_t)NTOK * DIMC / 8; i += stride) {
        float4 a = ((const float4*)x)[i * 2], b = ((const float4*)x)[i * 2 + 1];
        ((uint4*)g_xh)[i] = pack8f(a, b);
    }
}

// ---------------------------------------------------------------------------
// Fused kernel. Block roles by bid (dispatch order = dependency order):
//   [0, 240)      : Wg/Wi conversion producers, k-slab staggered -> g_kdone[kt]
//   [240, 384)    : Wo conversion -> g_wo_done
//   [384, 4992)   : gemm1 tiles (mt-major), gated on g_kdone frontier
//   [4992, 5568)  : gemm2 tiles, gated on g_tile_done[mt] + g_wo_done
// ---------------------------------------------------------------------------
__global__ void __launch_bounds__(256, 2) moe_gemms(
    const float* __restrict__ bg, const float* __restrict__ bi,
    const float* __restrict__ Wg, const float* __restrict__ Wi,
    const float* __restrict__ Wo, const float* __restrict__ bo,
    float* __restrict__ out)
{
    int bid = blockIdx.x;
    int tid = threadIdx.x;

    if (bid < NB_W) {
        // ---- Wg/Wi producers: ascending kt slabs, per-kt frontier publish ----
        for (int kt = 0; kt < NKT1; kt++) {
            // slab kt: 8e x 64k x 512 n8 = 262144 uint4 per matrix
            for (int u = bid * 256 + tid; u < 262144; u += NB_W * 256) {
                int e = u >> 15;
                int rem = u & 32767;
                int kr = rem >> 9;
                int n8 = rem & 511;
                size_t off = ((size_t)e * DIMC + kt * 64 + kr) * HIDC + n8 * 8;
                const float4* pg = (const float4*)(Wg + off);
                ((uint4*)g_whg)[off >> 3] = pack8f(pg[0], pg[1]);
                const float4* pi = (const float4*)(Wi + off);
                ((uint4*)g_whi)[off >> 3] = pack8f(pi[0], pi[1]);
            }
            __threadfence();
            __syncthreads();
            if (tid == 0) atomicAdd(&g_kdone[kt], 1);
        }
        if (tid == 0) {
            int p = atomicAdd(&g_prod_cnt, 1);
            if (p == NB_W - 1) { __threadfence(); g_all_done = 1; }
        }
        return;
    }

    if (bid < G1_0) {
        // ---- Wo conversion ----
        size_t t0 = (size_t)(bid - WO_0) * 256 + tid;
        const size_t stride = (size_t)NB_WO * 256;
#pragma unroll 4
        for (size_t i = t0; i < WSZ / 8; i += stride) {
            float4 a = ((const float4*)Wo)[i * 2];
            float4 b = ((const float4*)Wo)[i * 2 + 1];
            ((uint4*)g_who)[i] = pack8f(a, b);
        }
        __threadfence();
        __syncthreads();
        if (tid == 0) atomicAdd(&g_wo_done, 1);
        return;
    }

    extern __shared__ char smem[];
    uint32_t sb = su32(smem);
    int lane = tid & 31, wid = tid >> 5;
    int wm = wid & 1, wn = wid >> 1;
    int gq = lane >> 2, q = lane & 3;

    if (bid < G2_0) {
        // ================= GEMM1 tile =================
        int t = bid - G1_0;
        int mt = t >> 6, n0 = (t & 63) << 6;
        if (mt >= g_ntiles) return;
        int e = g_tile_expert[mt], row0 = g_tile_row0[mt], rows = g_tile_rows[mt];

        // block-uniform gate: tid 0 reads flag once, broadcast via smem
        __shared__ int s_gated;
        if (tid == 0) s_gated = (atomicAdd(&g_all_done, 0) == 0) ? 1 : 0;
        __syncthreads();
        bool gated = (s_gated != 0);
        __threadfence();

        float cg[4][2][4], ci[4][2][4];
#pragma unroll
        for (int i = 0; i < 4; i++)
#pragma unroll
            for (int j = 0; j < 2; j++)
#pragma unroll
                for (int k = 0; k < 4; k++) { cg[i][j][k] = 0.f; ci[i][j][k] = 0.f; }

        const __half* srcA[4];
        uint32_t dstA[4];
#pragma unroll
        for (int p = 0; p < 4; p++) {
            int c = tid + p * 256;
            int row = c >> 3, ch = c & 7;
            int gi = row0 + row; if (gi > NTOK - 1) gi = NTOK - 1;
            srcA[p] = g_xh + (size_t)g_order[gi] * DIMC + ch * 8;
            dstA[p] = row * 128 + ((ch ^ (row & 7)) << 4);
        }
        const __half *srcG[2], *srcI[2];
        uint32_t dstB[2];
#pragma unroll
        for (int p = 0; p < 2; p++) {
            int c = tid + p * 256;
            int kk = c >> 3, ch = c & 7;
            srcG[p] = g_whg + ((size_t)e * DIMC + kk) * HIDC + n0 + ch * 8;
            srcI[p] = g_whi + ((size_t)e * DIMC + kk) * HIDC + n0 + ch * 8;
            dstB[p] = kk * 128 + ((ch ^ (kk & 7)) << 4);
        }

        const int NKT = NKT1;  // 16
#define G1_ISSUE(KT) do { \
    uint32_t st_ = sb + ((KT) % 3) * 32768; int k0_ = (KT) * 64; \
    CP16(st_ + dstA[0], srcA[0] + k0_); \
    CP16(st_ + dstA[1], srcA[1] + k0_); \
    CP16(st_ + dstA[2], srcA[2] + k0_); \
    CP16(st_ + dstA[3], srcA[3] + k0_); \
    CP16(st_ + 16384 + dstB[0], srcG[0] + (size_t)k0_ * HIDC); \
    CP16(st_ + 16384 + dstB[1], srcG[1] + (size_t)k0_ * HIDC); \
    CP16(st_ + 24576 + dstB[0], srcI[0] + (size_t)k0_ * HIDC); \
    CP16(st_ + 24576 + dstB[1], srcI[1] + (size_t)k0_ * HIDC); \
} while (0)

        // prologue: frontier is monotone, covering k-tiles 0 and 1 via g_kdone[1]
        if (gated) {
            if (tid == 0)
                while (atomicAdd(&g_kdone[1], 0) < NB_W) __nanosleep(64);
            __syncthreads();
            __threadfence();
        }
        G1_ISSUE(0); CPCOMMIT();
        G1_ISSUE(1); CPCOMMIT();

        for (int kt = 0; kt < NKT; kt++) {
            CPWAIT1();
            __syncthreads();
            if (kt + 2 < NKT) {
                if (gated) {
                    if (tid == 0)
                        while (atomicAdd(&g_kdone[kt + 2], 0) < NB_W) __nanosleep(64);
                    __syncthreads();
                    __threadfence();
                }
                G1_ISSUE(kt + 2);
            }
            CPCOMMIT();
            uint32_t st = sb + (kt % 3) * 32768;
#pragma unroll
            for (int ks = 0; ks < 4; ks++) {
                uint32_t af[4][4], bgf[4], bif[4];
                int arow = wm * 64 + (lane & 15);
                int achk = 2 * ks + (lane >> 4);
#pragma unroll
                for (int mf = 0; mf < 4; mf++) {
                    int r = arow + mf * 16;
                    ldsm4(af[mf], st + r * 128 + ((achk ^ (r & 7)) << 4));
                }
                int bkr = ks * 16 + (lane & 15);
                int bchk = 2 * wn + (lane >> 4);
                uint32_t boff = bkr * 128 + ((bchk ^ (bkr & 7)) << 4);
                ldsm4t(bgf, st + 16384 + boff);
                ldsm4t(bif, st + 24576 + boff);
#pragma unroll
                for (int mf = 0; mf < 4; mf++) {
                    mma16816(cg[mf][0], af[mf], bgf + 0);
                    mma16816(cg[mf][1], af[mf], bgf + 2);
                    mma16816(ci[mf][0], af[mf], bif + 0);
                    mma16816(ci[mf][1], af[mf], bif + 2);
                }
            }
        }

        // epilogue: silu(g)*(v) -> g_hbuf (fp16, sorted rows)
        const float* bgp = bg + e * HIDC + n0;
        const float* bip = bi + e * HIDC + n0;
#pragma unroll
        for (int mf = 0; mf < 4; mf++) {
            int rl = wm * 64 + mf * 16 + gq;
#pragma unroll
            for (int nf = 0; nf < 2; nf++) {
                int col = wn * 16 + nf * 8 + q * 2;
                float bg0 = bgp[col], bg1 = bgp[col + 1];
                float bi0 = bip[col], bi1 = bip[col + 1];
                if (rl < rows) {
                    float g0 = cg[mf][nf][0] + bg0, g1 = cg[mf][nf][1] + bg1;
                    float v0 = ci[mf][nf][0] + bi0, v1 = ci[mf][nf][1] + bi1;
                    *(__half2*)&g_hbuf[(size_t)(row0 + rl) * HIDC + n0 + col] =
                        __floats2half2_rn(__fdividef(g0 * v0, 1.f + __expf(-g0)),
                                          __fdividef(g1 * v1, 1.f + __expf(-g1)));
                }
                if (rl + 8 < rows) {
                    float g0 = cg[mf][nf][2] + bg0, g1 = cg[mf][nf][3] + bg1;
                    float v0 = ci[mf][nf][2] + bi0, v1 = ci[mf][nf][3] + bi1;
                    *(__half2*)&g_hbuf[(size_t)(row0 + rl + 8) * HIDC + n0 + col] =
                        __floats2half2_rn(__fdividef(g0 * v0, 1.f + __expf(-g0)),
                                          __fdividef(g1 * v1, 1.f + __expf(-g1)));
                }
            }
        }
        __threadfence();
        __syncthreads();
        if (tid == 0) atomicAdd(&g_tile_done[mt], 1);
        return;
    }

    // ================= GEMM2 tile =================
    {
        int t = bid - G2_0;
        int mt = t >> 3, n0 = (t & 7) << 7;
        if (mt >= g_ntiles) return;
        int e = g_tile_expert[mt], row0 = g_tile_row0[mt], rows = g_tile_rows[mt];

        if (tid == 0) {
            while (atomicAdd(&g_wo_done, 0) < NB_WO) __nanosleep(64);
            while (atomicAdd(&g_tile_done[mt], 0) < 64) __nanosleep(64);
        }
        __syncthreads();
        __threadfence();

        float c[4][4][4];
#pragma unroll
        for (int i = 0; i < 4; i++)
#pragma unroll
            for (int j = 0; j < 4; j++)
#pragma unroll
                for (int k = 0; k < 4; k++) c[i][j][k] = 0.f;

        const __half* srcA[4];
        uint32_t dstA[4];
#pragma unroll
        for (int p = 0; p < 4; p++) {
            int cc = tid + p * 256;
            int row = cc >> 3, ch = cc & 7;
            srcA[p] = g_hbuf + (size_t)(row0 + row) * HIDC + ch * 8;
            dstA[p] = row * 128 + ((ch ^ (row & 7)) << 4);
        }
        const __half* srcB[4];
        uint32_t dstB[4];
#pragma unroll
        for (int p = 0; p < 4; p++) {
            int cc = tid + p * 256;
            int kk = cc >> 4, ch = cc & 15;
            srcB[p] = g_who + ((size_t)e * HIDC + kk) * DIMC + n0 + ch * 8;
            dstB[p] = kk * 256 + ((ch ^ (kk & 7)) << 4);
        }

        const int NKT = HIDC / 64;  // 64
#define G2_ISSUE(KT) do { \
    uint32_t st_ = sb + ((KT) % 3) * 32768; int k0_ = (KT) * 64; \
    CP16(st_ + dstA[0], srcA[0] + k0_); \
    CP16(st_ + dstA[1], srcA[1] + k0_); \
    CP16(st_ + dstA[2], srcA[2] + k0_); \
    CP16(st_ + dstA[3], srcA[3] + k0_); \
    CP16(st_ + 16384 + dstB[0], srcB[0] + (size_t)k0_ * DIMC); \
    CP16(st_ + 16384 + dstB[1], srcB[1] + (size_t)k0_ * DIMC); \
    CP16(st_ + 16384 + dstB[2], srcB[2] + (size_t)k0_ * DIMC); \
    CP16(st_ + 16384 + dstB[3], srcB[3] + (size_t)k0_ * DIMC); \
} while (0)

        G2_ISSUE(0); CPCOMMIT();
        G2_ISSUE(1); CPCOMMIT();

        for (int kt = 0; kt < NKT; kt++) {
            CPWAIT1();
            __syncthreads();
            if (kt + 2 < NKT) G2_ISSUE(kt + 2);
            CPCOMMIT();
            uint32_t st = sb + (kt % 3) * 32768;
#pragma unroll
            for (int ks = 0; ks < 4; ks++) {
                uint32_t af[4][4], bf[2][4];
                int arow = wm * 64 + (lane & 15);
                int achk = 2 * ks + (lane >> 4);
#pragma unroll
                for (int mf = 0; mf < 4; mf++) {
                    int r = arow + mf * 16;
                    ldsm4(af[mf], st + r * 128 + ((achk ^ (r & 7)) << 4));
                }
                int bkr = ks * 16 + (lane & 15);
#pragma unroll
                for (int h = 0; h < 2; h++) {
                    int bchk = 4 * wn + 2 * h + (lane >> 4);
                    ldsm4t(bf[h], st + 16384 + bkr * 256 + ((bchk ^ (bkr & 7)) << 4));
                }
#pragma unroll
                for (int mf = 0; mf < 4; mf++) {
                    mma16816(c[mf][0], af[mf], bf[0] + 0);
                    mma16816(c[mf][1], af[mf], bf[0] + 2);
                    mma16816(c[mf][2], af[mf], bf[1] + 0);
                    mma16816(c[mf][3], af[mf], bf[1] + 2);
                }
            }
        }

        // epilogue: scatter out[tok] = c + bo
        const float* bop = bo + e * DIMC + n0;
#pragma unroll
        for (int mf = 0; mf < 4; mf++) {
            int rl = wm * 64 + mf * 16 + gq;
            int tok0 = (rl < rows) ? g_order[row0 + rl] : -1;
            int tok1 = (rl + 8 < rows) ? g_order[row0 + rl + 8] : -1;
#pragma unroll
            for (int nf = 0; nf < 4; nf++) {
                int col = wn * 32 + nf * 8 + q * 2;
                float b0 = bop[col], b1 = bop[col + 1];
                if (tok0 >= 0)
                    *(float2*)&out[(size_t)tok0 * DIMC + n0 + col] =
                        make_float2(c[mf][nf][0] + b0, c[mf][nf][1] + b1);
                if (tok1 >= 0)
                    *(float2*)&out[(size_t)tok1 * DIMC + n0 + col] =
                        make_float2(c[mf][nf][2] + b0, c[mf][nf][3] + b1);
            }
        }
    }
}

// ---------------------------------------------------------------------------
extern "C" void kernel_launch(void* const* d_in, const int* in_sizes, int n_in,
                              void* d_out, int out_size) {
    const float* x   = (const float*)d_in[0];
    const int*   rm  = (const int*)d_in[1];
    const float* Win = (const float*)d_in[2];
    const float* bin = (const float*)d_in[3];
    const float* Wgt = (const float*)d_in[4];
    const float* bgt = (const float*)d_in[5];
    const float* Wo  = (const float*)d_in[6];
    const float* bo  = (const float*)d_in[7];
    float* out = (float*)d_out;

    cudaFuncSetAttribute(moe_gemms, cudaFuncAttributeMaxDynamicSharedMemorySize, 98304);

    x_route_kernel<<<513, 256>>>(x, rm);
    moe_gemms<<<NB_TOT, 256, 98304>>>(bgt, bin, Wgt, Win, Wo, bo, out);
}

// round 16
// speedup vs baseline: 1.2967x; 1.2967x over previous
#include <cuda_runtime.h>
#include <cuda_fp16.h>
#include <cstdint>

#define NTOK 8192
#define DIMC 1024
#define HIDC 4096
#define NEXP 8
#define BM 128
#define MAXT 72
#define WSZ (NEXP * DIMC * HIDC)

#define NB_WO 144
#define G1_0 NB_WO
#define NB_G1 (MAXT * 64)
#define G2_0 (G1_0 + NB_G1)
#define NB_G2 (MAXT * 8)
#define NB_TOT (G2_0 + NB_G2)

// ---------------- persistent device scratch ----------------
__device__ int g_order[NTOK];
__device__ int g_tile_expert[MAXT];
__device__ int g_tile_row0[MAXT];
__device__ int g_tile_rows[MAXT];
__device__ int g_ntiles;
__device__ int g_tile_done[MAXT];  // gemm1 column-blocks completed per m-tile
__device__ int g_wo_done;          // Wo conversion blocks completed
__device__ __half g_hbuf[(size_t)(NTOK + BM) * HIDC];  // zero-init pad rows
__device__ __half g_whg[WSZ];
__device__ __half g_whi[WSZ];
__device__ __half g_who[WSZ];
__device__ __half g_xh[NTOK * DIMC];

// ---------------- helpers ----------------
__device__ __forceinline__ uint32_t su32(const void* p) {
    uint32_t a;
    asm("{ .reg .u64 t; cvta.to.shared.u64 t, %1; cvt.u32.u64 %0, t; }" : "=r"(a) : "l"(p));
    return a;
}
__device__ __forceinline__ void ldsm4(uint32_t r[4], uint32_t a) {
    asm volatile("ldmatrix.sync.aligned.m8n8.x4.shared.b16 {%0,%1,%2,%3}, [%4];"
                 : "=r"(r[0]), "=r"(r[1]), "=r"(r[2]), "=r"(r[3]) : "r"(a));
}
__device__ __forceinline__ void ldsm4t(uint32_t r[4], uint32_t a) {
    asm volatile("ldmatrix.sync.aligned.m8n8.x4.trans.shared.b16 {%0,%1,%2,%3}, [%4];"
                 : "=r"(r[0]), "=r"(r[1]), "=r"(r[2]), "=r"(r[3]) : "r"(a));
}
__device__ __forceinline__ void mma16816(float c[4], const uint32_t a[4], const uint32_t* b) {
    asm volatile(
        "mma.sync.aligned.m16n8k16.row.col.f32.f16.f16.f32 "
        "{%0,%1,%2,%3}, {%4,%5,%6,%7}, {%8,%9}, {%0,%1,%2,%3};"
        : "+f"(c[0]), "+f"(c[1]), "+f"(c[2]), "+f"(c[3])
        : "r"(a[0]), "r"(a[1]), "r"(a[2]), "r"(a[3]), "r"(b[0]), "r"(b[1]));
}
__device__ __forceinline__ uint32_t f2h2(float a, float b) {
    __half2 h = __floats2half2_rn(a, b);
    return *(uint32_t*)&h;
}
__device__ __forceinline__ uint4 pack8f(const float4& u, const float4& v) {
    uint4 o;
    o.x = f2h2(u.x, u.y); o.y = f2h2(u.z, u.w);
    o.z = f2h2(v.x, v.y); o.w = f2h2(v.z, v.w);
    return o;
}
#define CP16(dst, src) asm volatile("cp.async.cg.shared.global [%0], [%1], 16;" :: "r"(dst), "l"(src))
#define CPCOMMIT() asm volatile("cp.async.commit_group;" ::: "memory")
#define CPWAIT1() asm volatile("cp.async.wait_group 1;" ::: "memory")

// ---------------- fused fp32->fp16 conversion (Wg, Wi, x) + routing ----------------
__global__ void __launch_bounds__(256) cvt_route_kernel(
    const float* __restrict__ Wg, const float* __restrict__ Wi,
    const float* __restrict__ x, const int* __restrict__ rm)
{
    __shared__ int cnt[NEXP], off[NEXP], cur[NEXP];
    int tid = threadIdx.x;
    if (blockIdx.x == gridDim.x - 1) {
        if (tid < MAXT) g_tile_done[tid] = 0;
        if (tid == 0) g_wo_done = 0;
        if (tid < NEXP) cnt[tid] = 0;
        __syncthreads();
        for (int i = tid; i < NTOK; i += blockDim.x) atomicAdd(&cnt[rm[i]], 1);
        __syncthreads();
        if (tid == 0) {
            int run = 0, nt = 0;
            for (int e = 0; e < NEXP; e++) {
                off[e] = run;
                int rem = cnt[e], r = run;
                while (rem > 0) {
                    g_tile_expert[nt] = e;
                    g_tile_row0[nt] = r;
                    g_tile_rows[nt] = rem < BM ? rem : BM;
                    r += BM; rem -= BM; nt++;
                }
                run += cnt[e];
            }
            g_ntiles = nt;
        }
        __syncthreads();
        if (tid < NEXP) cur[tid] = off[tid];
        __syncthreads();
        for (int i = tid; i < NTOK; i += blockDim.x) {
            int p = atomicAdd(&cur[rm[i]], 1);
            g_order[p] = i;
        }
        return;
    }
    size_t stride = (size_t)(gridDim.x - 1) * blockDim.x;
    size_t t0 = (size_t)blockIdx.x * blockDim.x + tid;
    for (size_t i = t0; i < WSZ / 8; i += stride) {
        float4 a, b;
        a = ((const float4*)Wg)[i * 2]; b = ((const float4*)Wg)[i * 2 + 1];
        ((uint4*)g_whg)[i] = pack8f(a, b);
        a = ((const float4*)Wi)[i * 2]; b = ((const float4*)Wi)[i * 2 + 1];
        ((uint4*)g_whi)[i] = pack8f(a, b);
    }
    for (size_t i = t0; i < (size_t)NTOK * DIMC / 8; i += stride) {
        float4 a = ((const float4*)x)[i * 2], b = ((const float4*)x)[i * 2 + 1];
        ((uint4*)g_xh)[i] = pack8f(a, b);
    }
}

// ---------------------------------------------------------------------------
// Fused GEMM kernel, 1D grid, dispatch-ordered pipeline:
//   bid [0, 144)        : Wo fp32->fp16 conversion          -> g_wo_done
//   bid [144, 144+4608) : gemm1 tiles, m-tile-major         -> g_tile_done[mt]
//   bid [4752, 5328)    : gemm2 tiles, spin on g_tile_done[mt]==64 && wo_done
// All blocks: 256 thr, 96KB smem, 2 CTAs/SM. Waits only target lower bids.
// ---------------------------------------------------------------------------
__global__ void __launch_bounds__(256, 2) moe_gemms(
    const float* __restrict__ bg, const float* __restrict__ bi,
    const float* __restrict__ Wo, const float* __restrict__ bo,
    float* __restrict__ out)
{
    int bid = blockIdx.x;
    int tid = threadIdx.x;

    if (bid < NB_WO) {
        // ---- Wo conversion ----
        size_t t0 = (size_t)bid * 256 + tid;
        const size_t stride = (size_t)NB_WO * 256;
#pragma unroll 4
        for (size_t i = t0; i < WSZ / 8; i += stride) {
            float4 a = ((const float4*)Wo)[i * 2];
            float4 b = ((const float4*)Wo)[i * 2 + 1];
            ((uint4*)g_who)[i] = pack8f(a, b);
        }
        __threadfence();
        __syncthreads();
        if (tid == 0) atomicAdd(&g_wo_done, 1);
        return;
    }

    extern __shared__ char smem[];
    uint32_t sb = su32(smem);
    int lane = tid & 31, wid = tid >> 5;
    int wm = wid & 1, wn = wid >> 1;
    int gq = lane >> 2, q = lane & 3;

    if (bid < G2_0) {
        // ================= GEMM1 tile =================
        int t = bid - G1_0;
        int mt = t >> 6, n0 = (t & 63) << 6;
        if (mt >= g_ntiles) return;
        int e = g_tile_expert[mt], row0 = g_tile_row0[mt], rows = g_tile_rows[mt];

        float cg[4][2][4], ci[4][2][4];
#pragma unroll
        for (int i = 0; i < 4; i++)
#pragma unroll
            for (int j = 0; j < 2; j++)
#pragma unroll
                for (int k = 0; k < 4; k++) { cg[i][j][k] = 0.f; ci[i][j][k] = 0.f; }

        const __half* srcA[4];
        uint32_t dstA[4];
#pragma unroll
        for (int p = 0; p < 4; p++) {
            int c = tid + p * 256;
            int row = c >> 3, ch = c & 7;
            int gi = row0 + row; if (gi > NTOK - 1) gi = NTOK - 1;
            srcA[p] = g_xh + (size_t)g_order[gi] * DIMC + ch * 8;
            dstA[p] = row * 128 + ((ch ^ (row & 7)) << 4);
        }
        const __half *srcG[2], *srcI[2];
        uint32_t dstB[2];
#pragma unroll
        for (int p = 0; p < 2; p++) {
            int c = tid + p * 256;
            int kk = c >> 3, ch = c & 7;
            srcG[p] = g_whg + ((size_t)e * DIMC + kk) * HIDC + n0 + ch * 8;
            srcI[p] = g_whi + ((size_t)e * DIMC + kk) * HIDC + n0 + ch * 8;
            dstB[p] = kk * 128 + ((ch ^ (kk & 7)) << 4);
        }

        const int NKT = DIMC / 64;  // 16
#define G1_ISSUE(KT) do { \
    uint32_t st_ = sb + ((KT) % 3) * 32768; int k0_ = (KT) * 64; \
    CP16(st_ + dstA[0], srcA[0] + k0_); \
    CP16(st_ + dstA[1], srcA[1] + k0_); \
    CP16(st_ + dstA[2], srcA[2] + k0_); \
    CP16(st_ + dstA[3], srcA[3] + k0_); \
    CP16(st_ + 16384 + dstB[0], srcG[0] + (size_t)k0_ * HIDC); \
    CP16(st_ + 16384 + dstB[1], srcG[1] + (size_t)k0_ * HIDC); \
    CP16(st_ + 24576 + dstB[0], srcI[0] + (size_t)k0_ * HIDC); \
    CP16(st_ + 24576 + dstB[1], srcI[1] + (size_t)k0_ * HIDC); \
} while (0)

        G1_ISSUE(0); CPCOMMIT();
        G1_ISSUE(1); CPCOMMIT();

        for (int kt = 0; kt < NKT; kt++) {
            CPWAIT1();
            __syncthreads();
            if (kt + 2 < NKT) G1_ISSUE(kt + 2);
            CPCOMMIT();
            uint32_t st = sb + (kt % 3) * 32768;
#pragma unroll
            for (int ks = 0; ks < 4; ks++) {
                uint32_t af[4][4], bgf[4], bif[4];
                int arow = wm * 64 + (lane & 15);
                int achk = 2 * ks + (lane >> 4);
#pragma unroll
                for (int mf = 0; mf < 4; mf++) {
                    int r = arow + mf * 16;
                    ldsm4(af[mf], st + r * 128 + ((achk ^ (r & 7)) << 4));
                }
                int bkr = ks * 16 + (lane & 15);
                int bchk = 2 * wn + (lane >> 4);
                uint32_t boff = bkr * 128 + ((bchk ^ (bkr & 7)) << 4);
                ldsm4t(bgf, st + 16384 + boff);
                ldsm4t(bif, st + 24576 + boff);
#pragma unroll
                for (int mf = 0; mf < 4; mf++) {
                    mma16816(cg[mf][0], af[mf], bgf + 0);
                    mma16816(cg[mf][1], af[mf], bgf + 2);
                    mma16816(ci[mf][0], af[mf], bif + 0);
                    mma16816(ci[mf][1], af[mf], bif + 2);
                }
            }
        }

        // epilogue: silu(g)*(v) -> g_hbuf (fp16, sorted rows)
        const float* bgp = bg + e * HIDC + n0;
        const float* bip = bi + e * HIDC + n0;
#pragma unroll
        for (int mf = 0; mf < 4; mf++) {
            int rl = wm * 64 + mf * 16 + gq;
#pragma unroll
            for (int nf = 0; nf < 2; nf++) {
                int col = wn * 16 + nf * 8 + q * 2;
                float bg0 = bgp[col], bg1 = bgp[col + 1];
                float bi0 = bip[col], bi1 = bip[col + 1];
                if (rl < rows) {
                    float g0 = cg[mf][nf][0] + bg0, g1 = cg[mf][nf][1] + bg1;
                    float v0 = ci[mf][nf][0] + bi0, v1 = ci[mf][nf][1] + bi1;
                    *(__half2*)&g_hbuf[(size_t)(row0 + rl) * HIDC + n0 + col] =
                        __floats2half2_rn(__fdividef(g0 * v0, 1.f + __expf(-g0)),
                                          __fdividef(g1 * v1, 1.f + __expf(-g1)));
                }
                if (rl + 8 < rows) {
                    float g0 = cg[mf][nf][2] + bg0, g1 = cg[mf][nf][3] + bg1;
                    float v0 = ci[mf][nf][2] + bi0, v1 = ci[mf][nf][3] + bi1;
                    *(__half2*)&g_hbuf[(size_t)(row0 + rl + 8) * HIDC + n0 + col] =
                        __floats2half2_rn(__fdividef(g0 * v0, 1.f + __expf(-g0)),
                                          __fdividef(g1 * v1, 1.f + __expf(-g1)));
                }
            }
        }
        __threadfence();
        __syncthreads();
        if (tid == 0) atomicAdd(&g_tile_done[mt], 1);
        return;
    }

    // ================= GEMM2 tile =================
    {
        int t = bid - G2_0;
        int mt = t >> 3, n0 = (t & 7) << 7;
        if (mt >= g_ntiles) return;
        int e = g_tile_expert[mt], row0 = g_tile_row0[mt], rows = g_tile_rows[mt];

        if (tid == 0) {
            while (atomicAdd(&g_wo_done, 0) < NB_WO) __nanosleep(64);
            while (atomicAdd(&g_tile_done[mt], 0) < 64) __nanosleep(64);
        }
        __syncthreads();
        __threadfence();

        float c[4][4][4];
#pragma unroll
        for (int i = 0; i < 4; i++)
#pragma unroll
            for (int j = 0; j < 4; j++)
#pragma unroll
                for (int k = 0; k < 4; k++) c[i][j][k] = 0.f;

        const __half* srcA[4];
        uint32_t dstA[4];
#pragma unroll
        for (int p = 0; p < 4; p++) {
            int cc = tid + p * 256;
            int row = cc >> 3, ch = cc & 7;
            srcA[p] = g_hbuf + (size_t)(row0 + row) * HIDC + ch * 8;
            dstA[p] = row * 128 + ((ch ^ (row & 7)) << 4);
        }
        const __half* srcB[4];
        uint32_t dstB[4];
#pragma unroll
        for (int p = 0; p < 4; p++) {
            int cc = tid + p * 256;
            int kk = cc >> 4, ch = cc & 15;
            srcB[p] = g_who + ((size_t)e * HIDC + kk) * DIMC + n0 + ch * 8;
            dstB[p] = kk * 256 + ((ch ^ (kk & 7)) << 4);
        }

        const int NKT = HIDC / 64;  // 64
#define G2_ISSUE(KT) do { \
    uint32_t st_ = sb + ((KT) % 3) * 32768; int k0_ = (KT) * 64; \
    CP16(st_ + dstA[0], srcA[0] + k0_); \
    CP16(st_ + dstA[1], srcA[1] + k0_); \
    CP16(st_ + dstA[2], srcA[2] + k0_); \
    CP16(st_ + dstA[3], srcA[3] + k0_); \
    CP16(st_ + 16384 + dstB[0], srcB[0] + (size_t)k0_ * DIMC); \
    CP16(st_ + 16384 + dstB[1], srcB[1] + (size_t)k0_ * DIMC); \
    CP16(st_ + 16384 + dstB[2], srcB[2] + (size_t)k0_ * DIMC); \
    CP16(st_ + 16384 + dstB[3], srcB[3] + (size_t)k0_ * DIMC); \
} while (0)

        G2_ISSUE(0); CPCOMMIT();
        G2_ISSUE(1); CPCOMMIT();

        for (int kt = 0; kt < NKT; kt++) {
            CPWAIT1();
            __syncthreads();
            if (kt + 2 < NKT) G2_ISSUE(kt + 2);
            CPCOMMIT();
            uint32_t st = sb + (kt % 3) * 32768;
#pragma unroll
            for (int ks = 0; ks < 4; ks++) {
                uint32_t af[4][4], bf[2][4];
                int arow = wm * 64 + (lane & 15);
                int achk = 2 * ks + (lane >> 4);
#pragma unroll
                for (int mf = 0; mf < 4; mf++) {
                    int r = arow + mf * 16;
                    ldsm4(af[mf], st + r * 128 + ((achk ^ (r & 7)) << 4));
                }
                int bkr = ks * 16 + (lane & 15);
#pragma unroll
                for (int h = 0; h < 2; h++) {
                    int bchk = 4 * wn + 2 * h + (lane >> 4);
                    ldsm4t(bf[h], st + 16384 + bkr * 256 + ((bchk ^ (bkr & 7)) << 4));
                }
#pragma unroll
                for (int mf = 0; mf < 4; mf++) {
                    mma16816(c[mf][0], af[mf], bf[0] + 0);
                    mma16816(c[mf][1], af[mf], bf[0] + 2);
                    mma16816(c[mf][2], af[mf], bf[1] + 0);
                    mma16816(c[mf][3], af[mf], bf[1] + 2);
                }
            }
        }

        // epilogue: scatter out[tok] = c + bo
        const float* bop = bo + e * DIMC + n0;
#pragma unroll
        for (int mf = 0; mf < 4; mf++) {
            int rl = wm * 64 + mf * 16 + gq;
            int tok0 = (rl < rows) ? g_order[row0 + rl] : -1;
            int tok1 = (rl + 8 < rows) ? g_order[row0 + rl + 8] : -1;
#pragma unroll
            for (int nf = 0; nf < 4; nf++) {
                int col = wn * 32 + nf * 8 + q * 2;
                float b0 = bop[col], b1 = bop[col + 1];
                if (tok0 >= 0)
                    *(float2*)&out[(size_t)tok0 * DIMC + n0 + col] =
                        make_float2(c[mf][nf][0] + b0, c[mf][nf][1] + b1);
                if (tok1 >= 0)
                    *(float2*)&out[(size_t)tok1 * DIMC + n0 + col] =
                        make_float2(c[mf][nf][2] + b0, c[mf][nf][3] + b1);
            }
        }
    }
}

// ---------------------------------------------------------------------------
extern "C" void kernel_launch(void* const* d_in, const int* in_sizes, int n_in,
                              void* d_out, int out_size) {
    const float* x   = (const float*)d_in[0];
    const int*   rm  = (const int*)d_in[1];
    const float* Win = (const float*)d_in[2];
    const float* bin = (const float*)d_in[3];
    const float* Wgt = (const float*)d_in[4];
    const float* bgt = (const float*)d_in[5];
    const float* Wo  = (const float*)d_in[6];
    const float* bo  = (const float*)d_in[7];
    float* out = (float*)d_out;

    cudaFuncSetAttribute(moe_gemms, cudaFuncAttributeMaxDynamicSharedMemorySize, 98304);

    cvt_route_kernel<<<2049, 256>>>(Wgt, Win, x, rm);
    moe_gemms<<<NB_TOT, 256, 98304>>>(bgt, bin, Wo, bo, out);
}

// round 17
// speedup vs baseline: 1.3050x; 1.0064x over previous
#include <cuda_runtime.h>
#include <cuda_fp16.h>
#include <cstdint>

#define NTOK 8192
#define DIMC 1024
#define HIDC 4096
#define NEXP 8
#define BM 128
#define MAXT 72
#define WSZ (NEXP * DIMC * HIDC)

#define NB_WO 144
#define G1_0 NB_WO
#define NB_G1 (MAXT * 64)
#define G2_0 (G1_0 + NB_G1)
#define NB_G2 (MAXT * 8)
#define NB_TOT (G2_0 + NB_G2)

// ---------------- persistent device scratch ----------------
__device__ int g_order[NTOK];
__device__ int g_tile_expert[MAXT];
__device__ int g_tile_row0[MAXT];
__device__ int g_tile_rows[MAXT];
__device__ int g_ntiles;
__device__ int g_tile_done[MAXT];  // gemm1 column-blocks completed per m-tile
__device__ int g_wo_done;          // Wo conversion blocks completed
__device__ __half g_hbuf[(size_t)(NTOK + BM) * HIDC];  // zero-init pad rows
__device__ __half g_whg[WSZ];
__device__ __half g_whi[WSZ];
__device__ __half g_who[WSZ];
__device__ __half g_xh[NTOK * DIMC];

// ---------------- helpers ----------------
__device__ __forceinline__ uint32_t su32(const void* p) {
    uint32_t a;
    asm("{ .reg .u64 t; cvta.to.shared.u64 t, %1; cvt.u32.u64 %0, t; }" : "=r"(a) : "l"(p));
    return a;
}
__device__ __forceinline__ void ldsm4(uint32_t r[4], uint32_t a) {
    asm volatile("ldmatrix.sync.aligned.m8n8.x4.shared.b16 {%0,%1,%2,%3}, [%4];"
                 : "=r"(r[0]), "=r"(r[1]), "=r"(r[2]), "=r"(r[3]) : "r"(a));
}
__device__ __forceinline__ void ldsm4t(uint32_t r[4], uint32_t a) {
    asm volatile("ldmatrix.sync.aligned.m8n8.x4.trans.shared.b16 {%0,%1,%2,%3}, [%4];"
                 : "=r"(r[0]), "=r"(r[1]), "=r"(r[2]), "=r"(r[3]) : "r"(a));
}
__device__ __forceinline__ void mma16816(float c[4], const uint32_t a[4], const uint32_t* b) {
    asm volatile(
        "mma.sync.aligned.m16n8k16.row.col.f32.f16.f16.f32 "
        "{%0,%1,%2,%3}, {%4,%5,%6,%7}, {%8,%9}, {%0,%1,%2,%3};"
        : "+f"(c[0]), "+f"(c[1]), "+f"(c[2]), "+f"(c[3])
        : "r"(a[0]), "r"(a[1]), "r"(a[2]), "r"(a[3]), "r"(b[0]), "r"(b[1]));
}
__device__ __forceinline__ uint32_t f2h2(float a, float b) {
    __half2 h = __floats2half2_rn(a, b);
    return *(uint32_t*)&h;
}
__device__ __forceinline__ uint4 pack8f(const float4& u, const float4& v) {
    uint4 o;
    o.x = f2h2(u.x, u.y); o.y = f2h2(u.z, u.w);
    o.z = f2h2(v.x, v.y); o.w = f2h2(v.z, v.w);
    return o;
}
#define CP16(dst, src) asm volatile("cp.async.cg.shared.global [%0], [%1], 16;" :: "r"(dst), "l"(src))
#define CPCOMMIT() asm volatile("cp.async.commit_group;" ::: "memory")
#define CPWAIT1() asm volatile("cp.async.wait_group 1;" ::: "memory")

// ---------------- fused fp32->fp16 conversion (Wg, Wi, x) + routing ----------------
__global__ void __launch_bounds__(256) cvt_route_kernel(
    const float* __restrict__ Wg, const float* __restrict__ Wi,
    const float* __restrict__ x, const int* __restrict__ rm)
{
    __shared__ int cnt[NEXP], off[NEXP], cur[NEXP];
    int tid = threadIdx.x;
    if (blockIdx.x == gridDim.x - 1) {
        if (tid < MAXT) g_tile_done[tid] = 0;
        if (tid == 0) g_wo_done = 0;
        if (tid < NEXP) cnt[tid] = 0;
        __syncthreads();
        for (int i = tid; i < NTOK; i += blockDim.x) atomicAdd(&cnt[rm[i]], 1);
        __syncthreads();
        if (tid == 0) {
            int run = 0, nt = 0;
            for (int e = 0; e < NEXP; e++) {
                off[e] = run;
                int rem = cnt[e], r = run;
                while (rem > 0) {
                    g_tile_expert[nt] = e;
                    g_tile_row0[nt] = r;
                    g_tile_rows[nt] = rem < BM ? rem : BM;
                    r += BM; rem -= BM; nt++;
                }
                run += cnt[e];
            }
            g_ntiles = nt;
        }
        __syncthreads();
        if (tid < NEXP) cur[tid] = off[tid];
        __syncthreads();
        for (int i = tid; i < NTOK; i += blockDim.x) {
            int p = atomicAdd(&cur[rm[i]], 1);
            g_order[p] = i;
        }
        return;
    }
    size_t stride = (size_t)(gridDim.x - 1) * blockDim.x;
    size_t t0 = (size_t)blockIdx.x * blockDim.x + tid;
    for (size_t i = t0; i < WSZ / 8; i += stride) {
        float4 a, b;
        a = ((const float4*)Wg)[i * 2]; b = ((const float4*)Wg)[i * 2 + 1];
        ((uint4*)g_whg)[i] = pack8f(a, b);
        a = ((const float4*)Wi)[i * 2]; b = ((const float4*)Wi)[i * 2 + 1];
        ((uint4*)g_whi)[i] = pack8f(a, b);
    }
    for (size_t i = t0; i < (size_t)NTOK * DIMC / 8; i += stride) {
        float4 a = ((const float4*)x)[i * 2], b = ((const float4*)x)[i * 2 + 1];
        ((uint4*)g_xh)[i] = pack8f(a, b);
    }
}

// ---------------------------------------------------------------------------
// Fused GEMM kernel, 1D grid, dispatch-ordered pipeline:
//   bid [0, 144)        : Wo fp32->fp16 conversion          -> g_wo_done
//   bid [144, 144+4608) : gemm1 tiles, m-tile-major         -> g_tile_done[mt]
//   bid [4752, 5328)    : gemm2 tiles, spin on g_tile_done[mt]==64 && wo_done
// All blocks: 256 thr, 96KB smem, 2 CTAs/SM. Waits only target lower bids.
// ---------------------------------------------------------------------------
__global__ void __launch_bounds__(256, 2) moe_gemms(
    const float* __restrict__ bg, const float* __restrict__ bi,
    const float* __restrict__ Wo, const float* __restrict__ bo,
    float* __restrict__ out)
{
    int bid = blockIdx.x;
    int tid = threadIdx.x;

    if (bid < NB_WO) {
        // ---- Wo conversion ----
        size_t t0 = (size_t)bid * 256 + tid;
        const size_t stride = (size_t)NB_WO * 256;
#pragma unroll 4
        for (size_t i = t0; i < WSZ / 8; i += stride) {
            float4 a = ((const float4*)Wo)[i * 2];
            float4 b = ((const float4*)Wo)[i * 2 + 1];
            ((uint4*)g_who)[i] = pack8f(a, b);
        }
        __threadfence();
        __syncthreads();
        if (tid == 0) atomicAdd(&g_wo_done, 1);
        return;
    }

    extern __shared__ char smem[];
    uint32_t sb = su32(smem);
    int lane = tid & 31, wid = tid >> 5;
    int wm = wid & 1, wn = wid >> 1;
    int gq = lane >> 2, q = lane & 3;

    if (bid < G2_0) {
        // ================= GEMM1 tile =================
        int t = bid - G1_0;
        int mt = t >> 6, n0 = (t & 63) << 6;
        if (mt >= g_ntiles) return;
        int e = g_tile_expert[mt], row0 = g_tile_row0[mt], rows = g_tile_rows[mt];

        float cg[4][2][4], ci[4][2][4];
#pragma unroll
        for (int i = 0; i < 4; i++)
#pragma unroll
            for (int j = 0; j < 2; j++)
#pragma unroll
                for (int k = 0; k < 4; k++) { cg[i][j][k] = 0.f; ci[i][j][k] = 0.f; }

        const __half* srcA[4];
        uint32_t dstA[4];
#pragma unroll
        for (int p = 0; p < 4; p++) {
            int c = tid + p * 256;
            int row = c >> 3, ch = c & 7;
            int gi = row0 + row; if (gi > NTOK - 1) gi = NTOK - 1;
            srcA[p] = g_xh + (size_t)g_order[gi] * DIMC + ch * 8;
            dstA[p] = row * 128 + ((ch ^ (row & 7)) << 4);
        }
        const __half *srcG[2], *srcI[2];
        uint32_t dstB[2];
#pragma unroll
        for (int p = 0; p < 2; p++) {
            int c = tid + p * 256;
            int kk = c >> 3, ch = c & 7;
            srcG[p] = g_whg + ((size_t)e * DIMC + kk) * HIDC + n0 + ch * 8;
            srcI[p] = g_whi + ((size_t)e * DIMC + kk) * HIDC + n0 + ch * 8;
            dstB[p] = kk * 128 + ((ch ^ (kk & 7)) << 4);
        }

        const int NKT = DIMC / 64;  // 16
#define G1_ISSUE(KT) do { \
    uint32_t st_ = sb + ((KT) % 3) * 32768; int k0_ = (KT) * 64; \
    CP16(st_ + dstA[0], srcA[0] + k0_); \
    CP16(st_ + dstA[1], srcA[1] + k0_); \
    CP16(st_ + dstA[2], srcA[2] + k0_); \
    CP16(st_ + dstA[3], srcA[3] + k0_); \
    CP16(st_ + 16384 + dstB[0], srcG[0] + (size_t)k0_ * HIDC); \
    CP16(st_ + 16384 + dstB[1], srcG[1] + (size_t)k0_ * HIDC); \
    CP16(st_ + 24576 + dstB[0], srcI[0] + (size_t)k0_ * HIDC); \
    CP16(st_ + 24576 + dstB[1], srcI[1] + (size_t)k0_ * HIDC); \
} while (0)

        G1_ISSUE(0); CPCOMMIT();
        G1_ISSUE(1); CPCOMMIT();

        for (int kt = 0; kt < NKT; kt++) {
            CPWAIT1();
            __syncthreads();
            if (kt + 2 < NKT) G1_ISSUE(kt + 2);
            CPCOMMIT();
            uint32_t st = sb + (kt % 3) * 32768;
#pragma unroll
            for (int ks = 0; ks < 4; ks++) {
                uint32_t af[4][4], bgf[4], bif[4];
                int arow = wm * 64 + (lane & 15);
                int achk = 2 * ks + (lane >> 4);
#pragma unroll
                for (int mf = 0; mf < 4; mf++) {
                    int r = arow + mf * 16;
                    ldsm4(af[mf], st + r * 128 + ((achk ^ (r & 7)) << 4));
                }
                int bkr = ks * 16 + (lane & 15);
                int bchk = 2 * wn + (lane >> 4);
                uint32_t boff = bkr * 128 + ((bchk ^ (bkr & 7)) << 4);
                ldsm4t(bgf, st + 16384 + boff);
                ldsm4t(bif, st + 24576 + boff);
#pragma unroll
                for (int mf = 0; mf < 4; mf++) {
                    mma16816(cg[mf][0], af[mf], bgf + 0);
                    mma16816(cg[mf][1], af[mf], bgf + 2);
                    mma16816(ci[mf][0], af[mf], bif + 0);
                    mma16816(ci[mf][1], af[mf], bif + 2);
                }
            }
        }

        // epilogue: silu(g)*(v) -> g_hbuf (fp16, sorted rows)
        const float* bgp = bg + e * HIDC + n0;
        const float* bip = bi + e * HIDC + n0;
#pragma unroll
        for (int mf = 0; mf < 4; mf++) {
            int rl = wm * 64 + mf * 16 + gq;
#pragma unroll
            for (int nf = 0; nf < 2; nf++) {
                int col = wn * 16 + nf * 8 + q * 2;
                float bg0 = bgp[col], bg1 = bgp[col + 1];
                float bi0 = bip[col], bi1 = bip[col + 1];
                if (rl < rows) {
                    float g0 = cg[mf][nf][0] + bg0, g1 = cg[mf][nf][1] + bg1;
                    float v0 = ci[mf][nf][0] + bi0, v1 = ci[mf][nf][1] + bi1;
                    *(__half2*)&g_hbuf[(size_t)(row0 + rl) * HIDC + n0 + col] =
                        __floats2half2_rn(__fdividef(g0 * v0, 1.f + __expf(-g0)),
                                          __fdividef(g1 * v1, 1.f + __expf(-g1)));
                }
                if (rl + 8 < rows) {
                    float g0 = cg[mf][nf][2] + bg0, g1 = cg[mf][nf][3] + bg1;
                    float v0 = ci[mf][nf][2] + bi0, v1 = ci[mf][nf][3] + bi1;
                    *(__half2*)&g_hbuf[(size_t)(row0 + rl + 8) * HIDC + n0 + col] =
                        __floats2half2_rn(__fdividef(g0 * v0, 1.f + __expf(-g0)),
                                          __fdividef(g1 * v1, 1.f + __expf(-g1)));
                }
            }
        }
        __threadfence();
        __syncthreads();
        if (tid == 0) atomicAdd(&g_tile_done[mt], 1);
        return;
    }

    // ================= GEMM2 tile =================
    {
        int t = bid - G2_0;
        int mt = t >> 3, n0 = (t & 7) << 7;
        if (mt >= g_ntiles) return;
        int e = g_tile_expert[mt], row0 = g_tile_row0[mt], rows = g_tile_rows[mt];

        if (tid == 0) {
            while (atomicAdd(&g_wo_done, 0) < NB_WO) __nanosleep(64);
            while (atomicAdd(&g_tile_done[mt], 0) < 64) __nanosleep(64);
        }
        __syncthreads();
        __threadfence();

        float c[4][4][4];
#pragma unroll
        for (int i = 0; i < 4; i++)
#pragma unroll
            for (int j = 0; j < 4; j++)
#pragma unroll
                for (int k = 0; k < 4; k++) c[i][j][k] = 0.f;

        const __half* srcA[4];
        uint32_t dstA[4];
#pragma unroll
        for (int p = 0; p < 4; p++) {
            int cc = tid + p * 256;
            int row = cc >> 3, ch = cc & 7;
            srcA[p] = g_hbuf + (size_t)(row0 + row) * HIDC + ch * 8;
            dstA[p] = row * 128 + ((ch ^ (row & 7)) << 4);
        }
        const __half* srcB[4];
        uint32_t dstB[4];
#pragma unroll
        for (int p = 0; p < 4; p++) {
            int cc = tid + p * 256;
            int kk = cc >> 4, ch = cc & 15;
            srcB[p] = g_who + ((size_t)e * HIDC + kk) * DIMC + n0 + ch * 8;
            dstB[p] = kk * 256 + ((ch ^ (kk & 7)) << 4);
        }

        const int NKT = HIDC / 64;  // 64
#define G2_ISSUE(KT) do { \
    uint32_t st_ = sb + ((KT) % 3) * 32768; int k0_ = (KT) * 64; \
    CP16(st_ + dstA[0], srcA[0] + k0_); \
    CP16(st_ + dstA[1], srcA[1] + k0_); \
    CP16(st_ + dstA[2], srcA[2] + k0_); \
    CP16(st_ + dstA[3], srcA[3] + k0_); \
    CP16(st_ + 16384 + dstB[0], srcB[0] + (size_t)k0_ * DIMC); \
    CP16(st_ + 16384 + dstB[1], srcB[1] + (size_t)k0_ * DIMC); \
    CP16(st_ + 16384 + dstB[2], srcB[2] + (size_t)k0_ * DIMC); \
    CP16(st_ + 16384 + dstB[3], srcB[3] + (size_t)k0_ * DIMC); \
} while (0)

        G2_ISSUE(0); CPCOMMIT();
        G2_ISSUE(1); CPCOMMIT();

        for (int kt = 0; kt < NKT; kt++) {
            CPWAIT1();
            __syncthreads();
            if (kt + 2 < NKT) G2_ISSUE(kt + 2);
            CPCOMMIT();
            uint32_t st = sb + (kt % 3) * 32768;
#pragma unroll
            for (int ks = 0; ks < 4; ks++) {
                uint32_t af[4][4], bf[2][4];
                int arow = wm * 64 + (lane & 15);
                int achk = 2 * ks + (lane >> 4);
#pragma unroll
                for (int mf = 0; mf < 4; mf++) {
                    int r = arow + mf * 16;
                    ldsm4(af[mf], st + r * 128 + ((achk ^ (r & 7)) << 4));
                }
                int bkr = ks * 16 + (lane & 15);
#pragma unroll
                for (int h = 0; h < 2; h++) {
                    int bchk = 4 * wn + 2 * h + (lane >> 4);
                    ldsm4t(bf[h], st + 16384 + bkr * 256 + ((bchk ^ (bkr & 7)) << 4));
                }
#pragma unroll
                for (int mf = 0; mf < 4; mf++) {
                    mma16816(c[mf][0], af[mf], bf[0] + 0);
                    mma16816(c[mf][1], af[mf], bf[0] + 2);
                    mma16816(c[mf][2], af[mf], bf[1] + 0);
                    mma16816(c[mf][3], af[mf], bf[1] + 2);
                }
            }
        }

        // epilogue: scatter out[tok] = c + bo
        const float* bop = bo + e * DIMC + n0;
#pragma unroll
        for (int mf = 0; mf < 4; mf++) {
            int rl = wm * 64 + mf * 16 + gq;
            int tok0 = (rl < rows) ? g_order[row0 + rl] : -1;
            int tok1 = (rl + 8 < rows) ? g_order[row0 + rl + 8] : -1;
#pragma unroll
            for (int nf = 0; nf < 4; nf++) {
                int col = wn * 32 + nf * 8 + q * 2;
                float b0 = bop[col], b1 = bop[col + 1];
                if (tok0 >= 0)
                    *(float2*)&out[(size_t)tok0 * DIMC + n0 + col] =
                        make_float2(c[mf][nf][0] + b0, c[mf][nf][1] + b1);
                if (tok1 >= 0)
                    *(float2*)&out[(size_t)tok1 * DIMC + n0 + col] =
                        make_float2(c[mf][nf][2] + b0, c[mf][nf][3] + b1);
            }
        }
    }
}

// ---------------------------------------------------------------------------
extern "C" void kernel_launch(void* const* d_in, const int* in_sizes, int n_in,
                              void* d_out, int out_size) {
    const float* x   = (const float*)d_in[0];
    const int*   rm  = (const int*)d_in[1];
    const float* Win = (const float*)d_in[2];
    const float* bin = (const float*)d_in[3];
    const float* Wgt = (const float*)d_in[4];
    const float* bgt = (const float*)d_in[5];
    const float* Wo  = (const float*)d_in[6];
    const float* bo  = (const float*)d_in[7];
    float* out = (float*)d_out;

    cudaFuncSetAttribute(moe_gemms, cudaFuncAttributeMaxDynamicSharedMemorySize, 98304);

    cvt_route_kernel<<<2049, 256>>>(Wgt, Win, x, rm);
    moe_gemms<<<NB_TOT, 256, 98304>>>(bgt, bin, Wo, bo, out);
}